// round 2
// baseline (speedup 1.0000x reference)
#include <cuda_runtime.h>
#include <math.h>
#include <stdint.h>

#define MU 0.02f
#define NBINS 10
#define NMAX 4194304

// Scratch (allocation-free rule: __device__ globals, zero-init .bss)
__device__ float2       g_loss_buf[NMAX];          // (g, loss) per row, 32 MB
__device__ unsigned int d_gmin_bits;               // fp32 bits; g >= 0 so uint order == float order
__device__ unsigned int d_gmax_bits;
__device__ double       d_bin_loss[NBINS];
__device__ unsigned int d_bin_cnt[NBINS];

// ---------------------------------------------------------------------------
__global__ void ghmr_init() {
    int t = threadIdx.x;
    if (t < NBINS) {
        d_bin_loss[t] = 0.0;
        d_bin_cnt[t]  = 0u;
    }
    if (t == 0) {
        d_gmin_bits = 0x7F800000u;  // +inf
        d_gmax_bits = 0x00000000u;  // 0.0f (g >= 0)
    }
}

// ---------------------------------------------------------------------------
// Pass 1: per-row g & loss, store packed, reduce min/max of g.
__global__ void ghmr_pass1(const float4* __restrict__ in,
                           const float4* __restrict__ tg, int n) {
    int tid    = blockIdx.x * blockDim.x + threadIdx.x;
    int stride = gridDim.x * blockDim.x;

    float lmin = __int_as_float(0x7F800000);  // +inf
    float lmax = 0.0f;

    for (int i = tid; i < n; i += stride) {
        float4 a = in[i];
        float4 b = tg[i];

        float d0 = a.x - b.x, d1 = a.y - b.y, d2 = a.z - b.z, d3 = a.w - b.w;
        float e0 = sqrtf(d0 * d0 + MU * MU);
        float e1 = sqrtf(d1 * d1 + MU * MU);
        float e2 = sqrtf(d2 * d2 + MU * MU);
        float e3 = sqrtf(d3 * d3 + MU * MU);

        float loss = ((e0 - MU) + (e1 - MU)) + ((e2 - MU) + (e3 - MU));
        float g = ((fabsf(d0) / e0 + fabsf(d1) / e1) +
                   (fabsf(d2) / e2 + fabsf(d3) / e3));

        g_loss_buf[i] = make_float2(g, loss);
        lmin = fminf(lmin, g);
        lmax = fmaxf(lmax, g);
    }

    // warp reduce
    #pragma unroll
    for (int o = 16; o > 0; o >>= 1) {
        lmin = fminf(lmin, __shfl_xor_sync(0xFFFFFFFFu, lmin, o));
        lmax = fmaxf(lmax, __shfl_xor_sync(0xFFFFFFFFu, lmax, o));
    }

    __shared__ float smin[8], smax[8];
    int lane = threadIdx.x & 31;
    int wid  = threadIdx.x >> 5;
    if (lane == 0) { smin[wid] = lmin; smax[wid] = lmax; }
    __syncthreads();

    if (wid == 0) {
        int nw = (blockDim.x + 31) >> 5;
        lmin = (lane < nw) ? smin[lane] : __int_as_float(0x7F800000);
        lmax = (lane < nw) ? smax[lane] : 0.0f;
        #pragma unroll
        for (int o = 4; o > 0; o >>= 1) {
            lmin = fminf(lmin, __shfl_xor_sync(0xFFFFFFFFu, lmin, o));
            lmax = fmaxf(lmax, __shfl_xor_sync(0xFFFFFFFFu, lmax, o));
        }
        if (lane == 0) {
            atomicMin(&d_gmin_bits, __float_as_uint(lmin));
            atomicMax(&d_gmax_bits, __float_as_uint(lmax));
        }
    }
}

// ---------------------------------------------------------------------------
// Pass 2: bin on g/(max-min). Per-thread register accumulators (no per-element
// atomics; bins are heavily skewed so shared atomics would serialize).
__global__ void ghmr_pass2(int n) {
    float        acc[NBINS];
    unsigned int cnt[NBINS];
    #pragma unroll
    for (int b = 0; b < NBINS; b++) { acc[b] = 0.0f; cnt[b] = 0u; }

    float gmax  = __uint_as_float(d_gmax_bits);
    float gmin  = __uint_as_float(d_gmin_bits);
    float range = gmax - gmin;

    int tid    = blockIdx.x * blockDim.x + threadIdx.x;
    int stride = gridDim.x * blockDim.x;

    for (int i = tid; i < n; i += stride) {
        float2 v  = g_loss_buf[i];
        float  gn = v.x / range;                       // same op order as reference
        int    b  = (int)floorf(gn * (float)NBINS);
        b = min(max(b, 0), NBINS - 1);
        #pragma unroll
        for (int k = 0; k < NBINS; k++) {              // unrolled select: no local-mem indexing
            if (k == b) { acc[k] += v.y; cnt[k]++; }
        }
    }

    // warp reduce each bin (sum in double from here on)
    __shared__ double       s_loss[NBINS];
    __shared__ unsigned int s_cnt[NBINS];
    if (threadIdx.x < NBINS) { s_loss[threadIdx.x] = 0.0; s_cnt[threadIdx.x] = 0u; }
    __syncthreads();

    int lane = threadIdx.x & 31;
    #pragma unroll
    for (int b = 0; b < NBINS; b++) {
        double a = (double)acc[b];
        unsigned int c = cnt[b];
        #pragma unroll
        for (int o = 16; o > 0; o >>= 1) {
            a += __shfl_xor_sync(0xFFFFFFFFu, a, o);
            c += __shfl_xor_sync(0xFFFFFFFFu, c, o);
        }
        if (lane == 0 && c) {
            atomicAdd(&s_loss[b], a);
            atomicAdd(&s_cnt[b], c);
        }
    }
    __syncthreads();

    if (threadIdx.x < NBINS) {
        if (s_cnt[threadIdx.x]) {
            atomicAdd(&d_bin_loss[threadIdx.x], s_loss[threadIdx.x]);
            atomicAdd(&d_bin_cnt[threadIdx.x],  s_cnt[threadIdx.x]);
        }
    }
}

// ---------------------------------------------------------------------------
// Finalize: out = (1/n_nonempty) * sum_b loss_sum[b]/count[b] / 64 / 4096
__global__ void ghmr_finalize(float* out) {
    if (threadIdx.x == 0) {
        double s = 0.0;
        int    nn = 0;
        #pragma unroll
        for (int b = 0; b < NBINS; b++) {
            unsigned int c = d_bin_cnt[b];
            if (c > 0) {
                nn++;
                s += d_bin_loss[b] / (double)c;
            }
        }
        if (nn < 1) nn = 1;
        double r = s / (double)nn / 64.0 / 4096.0;
        out[0] = (float)r;
    }
}

// ---------------------------------------------------------------------------
extern "C" void kernel_launch(void* const* d_in, const int* in_sizes, int n_in,
                              void* d_out, int out_size) {
    const float4* in = (const float4*)d_in[0];
    const float4* tg = (const float4*)d_in[1];
    int n = in_sizes[0] / 4;           // rows (channels = 4)
    if (n > NMAX) n = NMAX;

    ghmr_init<<<1, 32>>>();
    ghmr_pass1<<<4096, 256>>>(in, tg, n);
    ghmr_pass2<<<2048, 256>>>(n);
    ghmr_finalize<<<1, 32>>>((float*)d_out);
}